// round 10
// baseline (speedup 1.0000x reference)
#include <cuda_runtime.h>
#include <cuda_fp16.h>
#include <cstdint>

// Differential attention via mma.sync (HMMA fp16).
//   S  = Q K^T, P = exp2(S*0.125*log2e) (fixed-base softmax), O += P V
//   out = (O1/l1 - 0.8*O2/l2) * 0.2, causal.
// 128-thread CTAs (BR=32, 4 warps) with __launch_bounds__(128,2): two
// independent CTAs per SM decouple barrier stalls and phase-shift the
// MMA/LDSM vs softmax (MUFU/FMA) demand. Per-warp work identical to R9.

namespace {
constexpr int SEQ = 2048, DIM = 128;
constexpr int BR = 32, BC = 64;
constexpr int QBLKS = SEQ / BR;        // 64
constexpr int SSTR  = 272;             // bytes per 128-fp16 row (+16B pad)
constexpr uint32_t QHo = 0;            // Q [32][128] fp16 (8704 B)
constexpr uint32_t KB0 = 8704;         // buffer base
constexpr uint32_t BUFSZ = 34816;      // per-buffer: K + V (each 64x272)
__host__ __device__ constexpr uint32_t kh_(int b) { return KB0          + (uint32_t)b * BUFSZ; }
__host__ __device__ constexpr uint32_t vh_(int b) { return KB0 + 17408u + (uint32_t)b * BUFSZ; }
constexpr uint32_t LSo = 78336;        // l sums [2][32] f32
constexpr uint32_t SMEM_TOTAL = 78848; // ~77 KB -> 2 CTAs/SM
constexpr int OSTR = 528;              // f32 row stride (bytes) for O exchange
constexpr float EX2C = 0.18033688011112042f;  // log2(e)/8
constexpr float LAMBDA = 0.8f, OUT_SCALE = 0.2f;
}

__device__ __forceinline__ uint32_t smem_u32(const void* p) {
    uint32_t a;
    asm("{ .reg .u64 t; cvta.to.shared.u64 t, %1; cvt.u32.u64 %0, t; }" : "=r"(a) : "l"(p));
    return a;
}
__device__ __forceinline__ uint32_t pkh(float lo, float hi) {
    uint32_t r; asm("cvt.rn.f16x2.f32 %0, %1, %2;" : "=r"(r) : "f"(hi), "f"(lo)); return r;
}
__device__ __forceinline__ float ex2(float x) {
    float y; asm("ex2.approx.f32 %0, %1;" : "=f"(y) : "f"(x)); return y;
}
__device__ __forceinline__ void sts2(uint32_t a, uint32_t w0, uint32_t w1) {
    asm volatile("st.shared.v2.b32 [%0], {%1,%2};" :: "r"(a), "r"(w0), "r"(w1));
}
__device__ __forceinline__ void sts2f(uint32_t a, float x, float y) {
    asm volatile("st.shared.v2.f32 [%0], {%1,%2};" :: "r"(a), "f"(x), "f"(y));
}
__device__ __forceinline__ void ldsm4(uint32_t* r, uint32_t a) {
    asm volatile("ldmatrix.sync.aligned.m8n8.x4.shared.b16 {%0,%1,%2,%3}, [%4];"
        : "=r"(r[0]), "=r"(r[1]), "=r"(r[2]), "=r"(r[3]) : "r"(a));
}
__device__ __forceinline__ void ldsm4t(uint32_t* r, uint32_t a) {
    asm volatile("ldmatrix.sync.aligned.m8n8.x4.trans.shared.b16 {%0,%1,%2,%3}, [%4];"
        : "=r"(r[0]), "=r"(r[1]), "=r"(r[2]), "=r"(r[3]) : "r"(a));
}
__device__ __forceinline__ void mma16816(float* c, const uint32_t* a, const uint32_t* b) {
    asm volatile("mma.sync.aligned.m16n8k16.row.col.f32.f16.f16.f32 "
        "{%0,%1,%2,%3}, {%4,%5,%6,%7}, {%8,%9}, {%0,%1,%2,%3};"
        : "+f"(c[0]), "+f"(c[1]), "+f"(c[2]), "+f"(c[3])
        : "r"(a[0]), "r"(a[1]), "r"(a[2]), "r"(a[3]), "r"(b[0]), "r"(b[1]));
}

__global__ __launch_bounds__(128, 2)
void diff_attn_mma(const float* __restrict__ Q, const float* __restrict__ K,
                   const float* __restrict__ V, float* __restrict__ O) {
    extern __shared__ char smc[];
    const uint32_t sb = smem_u32(smc);
    const int tid  = threadIdx.x;
    const int lane = tid & 31;
    const int w    = tid >> 5;          // 0..3
    const int strm = w >> 1;            // 0: stream1 (d 0-63), 1: stream2 (d 64-127)
    const int mrow = (w & 1) << 4;      // warp's 16 q-rows within the 32-row tile

    const int qb  = QBLKS - 1 - blockIdx.x;   // heavy q-blocks first
    const int h   = blockIdx.y;
    const int kvh = h >> 2;

    const float* Qg = Q + ((size_t)h * SEQ + (size_t)qb * BR) * DIM;
    const float* Kg = K + (size_t)kvh * SEQ * DIM;
    const float* Vg = V + (size_t)kvh * SEQ * DIM;

    // ---- load Q once: f32 -> fp16 (32 rows x 128 d = 1024 float4) ----
    #pragma unroll
    for (int it = 0; it < 8; ++it) {
        int idx = tid + it * 128;
        int r = idx >> 5, c4 = idx & 31;
        float4 q = *(const float4*)(Qg + (size_t)r * DIM + 4 * c4);
        sts2(sb + QHo + (uint32_t)(r * SSTR + c4 * 8), pkh(q.x, q.y), pkh(q.z, q.w));
    }
    // ---- load K/V tile 0 into buffer 0 (64 rows x 128 d each) ----
    #pragma unroll
    for (int it = 0; it < 16; ++it) {
        int idx = tid + it * 128;
        int r = idx >> 5, c4 = idx & 31;
        uint32_t addr = (uint32_t)(r * SSTR + c4 * 8);
        float4 k4 = *(const float4*)(Kg + (size_t)r * DIM + 4 * c4);
        sts2(sb + kh_(0) + addr, pkh(k4.x, k4.y), pkh(k4.z, k4.w));
        float4 v4 = *(const float4*)(Vg + (size_t)r * DIM + 4 * c4);
        sts2(sb + vh_(0) + addr, pkh(v4.x, v4.y), pkh(v4.z, v4.w));
    }
    __syncthreads();

    const uint32_t d0 = (uint32_t)(strm * 128);   // byte offset of stream's 64 dims

    float o[16][4];                       // O accum: 16 rows x 128 d
    #pragma unroll
    for (int j = 0; j < 16; ++j) { o[j][0]=0.f; o[j][1]=0.f; o[j][2]=0.f; o[j][3]=0.f; }
    float lac0 = 0.f, lac1 = 0.f;

    const int nkb = (qb >> 1) + 1;        // kv tiles covering rows <= qb*32+31
    for (int kb = 0; kb < nkb; ++kb) {
        const int cur = kb & 1, nxt = cur ^ 1;
        const uint32_t KHc = kh_(0) + (uint32_t)cur * BUFSZ;
        const uint32_t VHc = KHc + 17408u;
        const uint32_t KHn = kh_(0) + (uint32_t)nxt * BUFSZ;
        const uint32_t VHn = KHn + 17408u;
        const bool pf = (kb + 1 < nkb);
        const bool diag = (kb == (qb >> 1));
        const int row0 = qb * BR + mrow + (lane >> 2);

        float c[8][4];
        #pragma unroll
        for (int j = 0; j < 8; ++j) { c[j][0]=0.f; c[j][1]=0.f; c[j][2]=0.f; c[j][3]=0.f; }

        // ---- S = Q K^T (single fp16) ----
        #pragma unroll
        for (int kk = 0; kk < 4; ++kk) {
            uint32_t aaddr = (uint32_t)((mrow + (lane & 15)) * SSTR) + d0
                           + (uint32_t)(kk * 32 + (lane >> 4) * 16);
            uint32_t ah[4];
            ldsm4(ah, sb + QHo + aaddr);
            #pragma unroll
            for (int jj = 0; jj < 4; ++jj) {
                uint32_t baddr = (uint32_t)((16 * jj + (lane & 7) + ((lane >> 4) << 3)) * SSTR)
                               + d0 + (uint32_t)(kk * 32 + ((lane >> 3) & 1) * 16);
                uint32_t bh[4];
                ldsm4(bh, sb + KHc + baddr);
                mma16816(c[2*jj],   ah, bh);
                mma16816(c[2*jj+1], ah, bh + 2);
            }
        }

        // ---- prefetch next K/V tile into nxt buffers (short reg liveness) ----
        if (pf) {
            const float* Kt = Kg + (size_t)(kb + 1) * BC * DIM;
            const float* Vt = Vg + (size_t)(kb + 1) * BC * DIM;
            #pragma unroll
            for (int it = 0; it < 16; ++it) {
                int idx = tid + it * 128;
                int r = idx >> 5, c4 = idx & 31;
                uint32_t addr = (uint32_t)(r * SSTR + c4 * 8);
                float4 k4 = *(const float4*)(Kt + (size_t)r * DIM + 4 * c4);
                sts2(sb + KHn + addr, pkh(k4.x, k4.y), pkh(k4.z, k4.w));
                float4 v4 = *(const float4*)(Vt + (size_t)r * DIM + 4 * c4);
                sts2(sb + VHn + addr, pkh(v4.x, v4.y), pkh(v4.z, v4.w));
            }
        }

        // ---- two pipelined halves: softmax+convert then PV ----
        #pragma unroll
        for (int half = 0; half < 2; ++half) {
            #pragma unroll
            for (int jx = 0; jx < 4; ++jx) {
                const int j = half * 4 + jx;
                int colb = kb * BC + 8 * j + 2 * (lane & 3);
                float p0 = ex2(c[j][0] * EX2C), p1 = ex2(c[j][1] * EX2C);
                float p2 = ex2(c[j][2] * EX2C), p3 = ex2(c[j][3] * EX2C);
                if (diag) {
                    if (colb     > row0)     p0 = 0.f;
                    if (colb + 1 > row0)     p1 = 0.f;
                    if (colb     > row0 + 8) p2 = 0.f;
                    if (colb + 1 > row0 + 8) p3 = 0.f;
                }
                c[j][0] = p0; c[j][1] = p1; c[j][2] = p2; c[j][3] = p3;
                lac0 += p0 + p1;
                lac1 += p2 + p3;
            }

            uint32_t ph[2][4];
            #pragma unroll
            for (int kx = 0; kx < 2; ++kx) {
                const int kk = half * 2 + kx;
                const float* f0 = c[2*kk];
                const float* f1 = c[2*kk+1];
                ph[kx][0] = pkh(f0[0], f0[1]);
                ph[kx][1] = pkh(f0[2], f0[3]);
                ph[kx][2] = pkh(f1[0], f1[1]);
                ph[kx][3] = pkh(f1[2], f1[3]);
            }

            #pragma unroll
            for (int kx = 0; kx < 2; ++kx) {
                const int kk = half * 2 + kx;
                #pragma unroll
                for (int jj = 0; jj < 8; ++jj) {
                    uint32_t vaddr = (uint32_t)((16 * kk + (lane & 15)) * SSTR)
                                   + (uint32_t)(jj * 32 + (lane >> 4) * 16);
                    uint32_t vh4[4];
                    ldsm4t(vh4, sb + VHc + vaddr);
                    mma16816(o[2*jj],   ph[kx], vh4);
                    mma16816(o[2*jj+1], ph[kx], vh4 + 2);
                }
            }
        }
        __syncthreads();   // cur buffer reads done; nxt buffer writes visible
    }

    // ---- epilogue: O frags -> smem (f32), l sums, combine streams ----
    const uint32_t ob = sb + (strm ? kh_(1) : kh_(0));   // reuse K/V regions
    const int r0 = mrow + (lane >> 2);
    #pragma unroll
    for (int j = 0; j < 16; ++j) {
        uint32_t cb = (uint32_t)((8 * j + 2 * (lane & 3)) * 4);
        sts2f(ob + (uint32_t)(r0 * OSTR) + cb,       o[j][0], o[j][1]);
        sts2f(ob + (uint32_t)((r0 + 8) * OSTR) + cb, o[j][2], o[j][3]);
    }
    lac0 += __shfl_xor_sync(0xffffffffu, lac0, 1);
    lac0 += __shfl_xor_sync(0xffffffffu, lac0, 2);
    lac1 += __shfl_xor_sync(0xffffffffu, lac1, 1);
    lac1 += __shfl_xor_sync(0xffffffffu, lac1, 2);
    float* ls = (float*)(smc + LSo);
    if ((lane & 3) == 0) {
        ls[strm * 32 + r0]     = lac0;
        ls[strm * 32 + r0 + 8] = lac1;
    }
    __syncthreads();

    const int er = tid >> 2;            // 0..31
    const int cq = (tid & 3) * 32;
    const float i1 = OUT_SCALE / ls[er];
    const float i2 = OUT_SCALE * LAMBDA / ls[32 + er];
    float* Og = O + ((size_t)h * SEQ + (size_t)qb * BR + er) * DIM + cq;
    #pragma unroll
    for (int u = 0; u < 8; ++u) {
        float4 a = *(const float4*)(smc + kh_(0) + er * OSTR + (cq + 4 * u) * 4);
        float4 b = *(const float4*)(smc + kh_(1) + er * OSTR + (cq + 4 * u) * 4);
        float4 ov;
        ov.x = a.x * i1 - b.x * i2;
        ov.y = a.y * i1 - b.y * i2;
        ov.z = a.z * i1 - b.z * i2;
        ov.w = a.w * i1 - b.w * i2;
        *(float4*)(Og + 4 * u) = ov;
    }
}

extern "C" void kernel_launch(void* const* d_in, const int* in_sizes, int n_in,
                              void* d_out, int out_size) {
    const float* Q = (const float*)d_in[0];
    const float* K = (const float*)d_in[1];
    const float* V = (const float*)d_in[2];
    float* O = (float*)d_out;

    cudaFuncSetAttribute(diff_attn_mma,
                         cudaFuncAttributeMaxDynamicSharedMemorySize, SMEM_TOTAL);
    dim3 grid(QBLKS, 16);   // (64, 16) = 1024 CTAs of 128 threads, heavy first
    diff_attn_mma<<<grid, 128, SMEM_TOTAL>>>(Q, K, V, O);
}

// round 11
// speedup vs baseline: 1.1001x; 1.1001x over previous
#include <cuda_runtime.h>
#include <cuda_fp16.h>
#include <cstdint>

// Differential attention via mma.sync (HMMA fp16).
//   S = Q K^T, P = exp2(S*0.125*log2e) (fixed-base softmax), O += P V
//   out = (O1/l1 - 0.8*O2/l2) * 0.2, causal.
// Cross-tile pipelining: S(kb+1) interleaved with PV(kb) (independent MMA
// chains), triple-buffered K/V, one syncthreads per tile.

namespace {
constexpr int SEQ = 2048, DIM = 128;
constexpr int BR = 64, BC = 64;
constexpr int QBLKS = SEQ / BR;        // 32
constexpr int SSTR  = 272;             // bytes per 128-fp16 row (+16B pad)
constexpr uint32_t QHo = 0;            // Q [64][128] fp16
constexpr uint32_t KB0 = 17408;        // buffer base
constexpr uint32_t BUFSZ = 34816;      // per-buffer: K + V
__host__ __device__ constexpr uint32_t kh_(int b) { return KB0          + (uint32_t)b * BUFSZ; }
__host__ __device__ constexpr uint32_t vh_(int b) { return KB0 + 17408u + (uint32_t)b * BUFSZ; }
constexpr uint32_t LSo = 121856;       // l sums [2][64] f32
constexpr uint32_t SMEM_TOTAL = 122368;
constexpr int OSTR = 528;              // f32 row stride (bytes) for O exchange
constexpr float EX2C = 0.18033688011112042f;  // log2(e)/8
constexpr float LAMBDA = 0.8f, OUT_SCALE = 0.2f;
}

__device__ __forceinline__ uint32_t smem_u32(const void* p) {
    uint32_t a;
    asm("{ .reg .u64 t; cvta.to.shared.u64 t, %1; cvt.u32.u64 %0, t; }" : "=r"(a) : "l"(p));
    return a;
}
__device__ __forceinline__ uint32_t pkh(float lo, float hi) {
    uint32_t r; asm("cvt.rn.f16x2.f32 %0, %1, %2;" : "=r"(r) : "f"(hi), "f"(lo)); return r;
}
__device__ __forceinline__ float ex2(float x) {
    float y; asm("ex2.approx.f32 %0, %1;" : "=f"(y) : "f"(x)); return y;
}
__device__ __forceinline__ void sts2(uint32_t a, uint32_t w0, uint32_t w1) {
    asm volatile("st.shared.v2.b32 [%0], {%1,%2};" :: "r"(a), "r"(w0), "r"(w1));
}
__device__ __forceinline__ void sts2f(uint32_t a, float x, float y) {
    asm volatile("st.shared.v2.f32 [%0], {%1,%2};" :: "r"(a), "f"(x), "f"(y));
}
__device__ __forceinline__ void ldsm4(uint32_t* r, uint32_t a) {
    asm volatile("ldmatrix.sync.aligned.m8n8.x4.shared.b16 {%0,%1,%2,%3}, [%4];"
        : "=r"(r[0]), "=r"(r[1]), "=r"(r[2]), "=r"(r[3]) : "r"(a));
}
__device__ __forceinline__ void ldsm4t(uint32_t* r, uint32_t a) {
    asm volatile("ldmatrix.sync.aligned.m8n8.x4.trans.shared.b16 {%0,%1,%2,%3}, [%4];"
        : "=r"(r[0]), "=r"(r[1]), "=r"(r[2]), "=r"(r[3]) : "r"(a));
}
__device__ __forceinline__ void mma16816(float* c, const uint32_t* a, const uint32_t* b) {
    asm volatile("mma.sync.aligned.m16n8k16.row.col.f32.f16.f16.f32 "
        "{%0,%1,%2,%3}, {%4,%5,%6,%7}, {%8,%9}, {%0,%1,%2,%3};"
        : "+f"(c[0]), "+f"(c[1]), "+f"(c[2]), "+f"(c[3])
        : "r"(a[0]), "r"(a[1]), "r"(a[2]), "r"(a[3]), "r"(b[0]), "r"(b[1]));
}

// ---- building blocks ----
__device__ __forceinline__ void s_tile(float c[8][4], uint32_t sb, uint32_t KH,
                                       uint32_t d0, int mrow, int lane) {
    #pragma unroll
    for (int kk = 0; kk < 4; ++kk) {
        uint32_t aaddr = (uint32_t)((mrow + (lane & 15)) * SSTR) + d0
                       + (uint32_t)(kk * 32 + (lane >> 4) * 16);
        uint32_t ah[4];
        ldsm4(ah, sb + QHo + aaddr);
        #pragma unroll
        for (int jj = 0; jj < 4; ++jj) {
            uint32_t baddr = (uint32_t)((16 * jj + (lane & 7) + ((lane >> 4) << 3)) * SSTR)
                           + d0 + (uint32_t)(kk * 32 + ((lane >> 3) & 1) * 16);
            uint32_t bh[4];
            ldsm4(bh, KH + baddr);
            mma16816(c[2*jj],   ah, bh);
            mma16816(c[2*jj+1], ah, bh + 2);
        }
    }
}
__device__ __forceinline__ void pv_tile(float o[16][4], const uint32_t ph[4][4],
                                        uint32_t VH, int lane) {
    #pragma unroll
    for (int kk = 0; kk < 4; ++kk) {
        #pragma unroll
        for (int jj = 0; jj < 8; ++jj) {
            uint32_t vaddr = (uint32_t)((16 * kk + (lane & 15)) * SSTR)
                           + (uint32_t)(jj * 32 + (lane >> 4) * 16);
            uint32_t vh4[4];
            ldsm4t(vh4, VH + vaddr);
            mma16816(o[2*jj],   ph[kk], vh4);
            mma16816(o[2*jj+1], ph[kk], vh4 + 2);
        }
    }
}
__device__ __forceinline__ void softmax_tile(float c[8][4], uint32_t ph[4][4],
                                             float& lac0, float& lac1,
                                             int kb, bool diag, int row0, int lane) {
    #pragma unroll
    for (int j = 0; j < 8; ++j) {
        int colb = kb * BC + 8 * j + 2 * (lane & 3);
        float p0 = ex2(c[j][0] * EX2C), p1 = ex2(c[j][1] * EX2C);
        float p2 = ex2(c[j][2] * EX2C), p3 = ex2(c[j][3] * EX2C);
        if (diag) {
            if (colb     > row0)     p0 = 0.f;
            if (colb + 1 > row0)     p1 = 0.f;
            if (colb     > row0 + 8) p2 = 0.f;
            if (colb + 1 > row0 + 8) p3 = 0.f;
        }
        c[j][0] = p0; c[j][1] = p1; c[j][2] = p2; c[j][3] = p3;
        lac0 += p0 + p1;
        lac1 += p2 + p3;
    }
    #pragma unroll
    for (int kk = 0; kk < 4; ++kk) {
        const float* f0 = c[2*kk];
        const float* f1 = c[2*kk+1];
        ph[kk][0] = pkh(f0[0], f0[1]);
        ph[kk][1] = pkh(f0[2], f0[3]);
        ph[kk][2] = pkh(f1[0], f1[1]);
        ph[kk][3] = pkh(f1[2], f1[3]);
    }
}
__device__ __forceinline__ void prefetch_kv(uint32_t sb, uint32_t KHn, uint32_t VHn,
                                            const float* Kt, const float* Vt, int tid) {
    #pragma unroll
    for (int it = 0; it < 8; ++it) {
        int idx = tid + it * 256;
        int r = idx >> 5, c4 = idx & 31;
        uint32_t addr = (uint32_t)(r * SSTR + c4 * 8);
        float4 k4 = *(const float4*)(Kt + (size_t)r * DIM + 4 * c4);
        sts2(KHn + addr, pkh(k4.x, k4.y), pkh(k4.z, k4.w));
        float4 v4 = *(const float4*)(Vt + (size_t)r * DIM + 4 * c4);
        sts2(VHn + addr, pkh(v4.x, v4.y), pkh(v4.z, v4.w));
    }
}

__global__ __launch_bounds__(256, 1)
void diff_attn_mma(const float* __restrict__ Q, const float* __restrict__ K,
                   const float* __restrict__ V, float* __restrict__ O) {
    extern __shared__ char smc[];
    const uint32_t sb = smem_u32(smc);
    const int tid  = threadIdx.x;
    const int lane = tid & 31;
    const int w    = tid >> 5;
    const int strm = w >> 2;            // 0: stream1 (d 0-63), 1: stream2 (d 64-127)
    const int mrow = (w & 3) << 4;      // warp's 16 q-rows within the 64-row tile

    const int qb  = QBLKS - 1 - blockIdx.x;   // heavy q-blocks first
    const int h   = blockIdx.y;
    const int kvh = h >> 2;

    const float* Qg = Q + ((size_t)h * SEQ + (size_t)qb * BR) * DIM;
    const float* Kg = K + (size_t)kvh * SEQ * DIM;
    const float* Vg = V + (size_t)kvh * SEQ * DIM;

    // ---- load Q once: f32 -> fp16 ----
    #pragma unroll
    for (int it = 0; it < 8; ++it) {
        int idx = tid + it * 256;
        int r = idx >> 5, c4 = idx & 31;
        float4 q = *(const float4*)(Qg + (size_t)r * DIM + 4 * c4);
        sts2(sb + QHo + (uint32_t)(r * SSTR + c4 * 8), pkh(q.x, q.y), pkh(q.z, q.w));
    }
    // ---- load K/V tile 0 into buffer 0 ----
    prefetch_kv(sb, sb + kh_(0), sb + vh_(0), Kg, Vg, tid);
    __syncthreads();

    const uint32_t d0 = (uint32_t)(strm * 128);
    const int row0 = qb * BR + mrow + (lane >> 2);
    const int nkb = qb + 1;

    float o[16][4];
    #pragma unroll
    for (int j = 0; j < 16; ++j) { o[j][0]=0.f; o[j][1]=0.f; o[j][2]=0.f; o[j][3]=0.f; }
    float lac0 = 0.f, lac1 = 0.f;
    uint32_t ph[4][4];

    // ---- prologue: S(0), prefetch(1), softmax(0) ----
    {
        float c[8][4];
        #pragma unroll
        for (int j = 0; j < 8; ++j) { c[j][0]=0.f; c[j][1]=0.f; c[j][2]=0.f; c[j][3]=0.f; }
        s_tile(c, sb, sb + kh_(0), d0, mrow, lane);
        if (nkb > 1)
            prefetch_kv(sb, sb + kh_(1), sb + vh_(1),
                        Kg + (size_t)BC * DIM, Vg + (size_t)BC * DIM, tid);
        softmax_tile(c, ph, lac0, lac1, 0, nkb == 1, row0, lane);
    }
    __syncthreads();

    // ---- pipelined main loop: S(kb+1) interleaved with PV(kb) ----
    for (int kb = 0; kb + 1 < nkb; ++kb) {
        const uint32_t KHn1 = sb + kh_((kb + 1) % 3);   // K for S(kb+1)
        const uint32_t VHc  = sb + vh_(kb % 3);         // V for PV(kb)
        float c[8][4];
        #pragma unroll
        for (int j = 0; j < 8; ++j) { c[j][0]=0.f; c[j][1]=0.f; c[j][2]=0.f; c[j][3]=0.f; }

        // interleave at kk granularity: S chain and PV chain are independent
        #pragma unroll
        for (int kk = 0; kk < 4; ++kk) {
            // S(kb+1) slice kk
            uint32_t aaddr = (uint32_t)((mrow + (lane & 15)) * SSTR) + d0
                           + (uint32_t)(kk * 32 + (lane >> 4) * 16);
            uint32_t ah[4];
            ldsm4(ah, sb + QHo + aaddr);
            #pragma unroll
            for (int jj = 0; jj < 4; ++jj) {
                uint32_t baddr = (uint32_t)((16 * jj + (lane & 7) + ((lane >> 4) << 3)) * SSTR)
                               + d0 + (uint32_t)(kk * 32 + ((lane >> 3) & 1) * 16);
                uint32_t bh[4];
                ldsm4(bh, KHn1 + baddr);
                mma16816(c[2*jj],   ah, bh);
                mma16816(c[2*jj+1], ah, bh + 2);
            }
            // PV(kb) slice kk
            #pragma unroll
            for (int jj = 0; jj < 8; ++jj) {
                uint32_t vaddr = (uint32_t)((16 * kk + (lane & 15)) * SSTR)
                               + (uint32_t)(jj * 32 + (lane >> 4) * 16);
                uint32_t vh4[4];
                ldsm4t(vh4, VHc + vaddr);
                mma16816(o[2*jj],   ph[kk], vh4);
                mma16816(o[2*jj+1], ph[kk], vh4 + 2);
            }
        }

        // prefetch tile kb+2 into buffer (kb+2)%3 (nobody reads it this iter)
        if (kb + 2 < nkb)
            prefetch_kv(sb, sb + kh_((kb + 2) % 3), sb + vh_((kb + 2) % 3),
                        Kg + (size_t)(kb + 2) * BC * DIM,
                        Vg + (size_t)(kb + 2) * BC * DIM, tid);

        // softmax(kb+1) -> new ph
        softmax_tile(c, ph, lac0, lac1, kb + 1, (kb + 2 == nkb), row0, lane);

        __syncthreads();
    }

    // ---- epilogue PV for last tile ----
    pv_tile(o, ph, sb + vh_((nkb - 1) % 3), lane);
    __syncthreads();   // all V reads done before O overwrites buffers

    // ---- epilogue: O frags -> smem (f32), l sums, combine streams ----
    const uint32_t ob = sb + (strm ? kh_(1) : kh_(0));
    const int r0 = mrow + (lane >> 2);
    #pragma unroll
    for (int j = 0; j < 16; ++j) {
        uint32_t cb = (uint32_t)((8 * j + 2 * (lane & 3)) * 4);
        sts2f(ob + (uint32_t)(r0 * OSTR) + cb,       o[j][0], o[j][1]);
        sts2f(ob + (uint32_t)((r0 + 8) * OSTR) + cb, o[j][2], o[j][3]);
    }
    lac0 += __shfl_xor_sync(0xffffffffu, lac0, 1);
    lac0 += __shfl_xor_sync(0xffffffffu, lac0, 2);
    lac1 += __shfl_xor_sync(0xffffffffu, lac1, 1);
    lac1 += __shfl_xor_sync(0xffffffffu, lac1, 2);
    float* ls = (float*)(smc + LSo);
    if ((lane & 3) == 0) {
        ls[strm * 64 + r0]     = lac0;
        ls[strm * 64 + r0 + 8] = lac1;
    }
    __syncthreads();

    const int er = tid >> 2;
    const int cq = (tid & 3) * 32;
    const float i1 = OUT_SCALE / ls[er];
    const float i2 = OUT_SCALE * LAMBDA / ls[64 + er];
    float* Og = O + ((size_t)h * SEQ + (size_t)qb * BR + er) * DIM + cq;
    #pragma unroll
    for (int u = 0; u < 8; ++u) {
        float4 a = *(const float4*)(smc + kh_(0) + er * OSTR + (cq + 4 * u) * 4);
        float4 b = *(const float4*)(smc + kh_(1) + er * OSTR + (cq + 4 * u) * 4);
        float4 ov;
        ov.x = a.x * i1 - b.x * i2;
        ov.y = a.y * i1 - b.y * i2;
        ov.z = a.z * i1 - b.z * i2;
        ov.w = a.w * i1 - b.w * i2;
        *(float4*)(Og + 4 * u) = ov;
    }
}

extern "C" void kernel_launch(void* const* d_in, const int* in_sizes, int n_in,
                              void* d_out, int out_size) {
    const float* Q = (const float*)d_in[0];
    const float* K = (const float*)d_in[1];
    const float* V = (const float*)d_in[2];
    float* O = (float*)d_out;

    cudaFuncSetAttribute(diff_attn_mma,
                         cudaFuncAttributeMaxDynamicSharedMemorySize, SMEM_TOTAL);
    dim3 grid(QBLKS, 16);   // (32, 16) = 512 CTAs, heavy first
    diff_attn_mma<<<grid, 256, SMEM_TOTAL>>>(Q, K, V, O);
}

// round 13
// speedup vs baseline: 1.1991x; 1.0900x over previous
#include <cuda_runtime.h>
#include <cuda_fp16.h>
#include <cstdint>

// Differential attention via mma.sync (HMMA fp16).
//   S = Q K^T, P = exp2(S*0.125*log2e) (fixed-base softmax), O += P V
//   out = (O1/l1 - 0.8*O2/l2) * 0.2, causal.
// Pre-pass converts Q/K/V f32->fp16 ONCE into __device__ buffers (was done
// per-CTA, ~66x duplicated for K/V); main loop streams tiles via cp.async
// (LDGSTS: no registers, no cvt in loop). R9 flow otherwise (best so far).

namespace {
constexpr int SEQ = 2048, DIM = 128;
constexpr int BR = 64, BC = 64;
constexpr int QBLKS = SEQ / BR;        // 32
constexpr int SSTR  = 272;             // bytes per 128-fp16 row (+16B pad)
constexpr uint32_t QHo = 0;            // Q [64][128] fp16
constexpr uint32_t KB0 = 17408;        // buffer base
constexpr uint32_t BUFSZ = 34816;      // per-buffer: K + V
__host__ __device__ constexpr uint32_t kh_(int b) { return KB0          + (uint32_t)b * BUFSZ; }
__host__ __device__ constexpr uint32_t vh_(int b) { return KB0 + 17408u + (uint32_t)b * BUFSZ; }
constexpr uint32_t LSo = 87040;        // l sums [2][64] f32
constexpr uint32_t SMEM_TOTAL = 87552;
constexpr int OSTR = 528;              // f32 row stride (bytes) for O exchange
constexpr float EX2C = 0.18033688011112042f;  // log2(e)/8
constexpr float LAMBDA = 0.8f, OUT_SCALE = 0.2f;
}

// fp16 copies (static device memory; no runtime allocation)
__device__ __half g_q16[16 * SEQ * DIM];   // 8 MB
__device__ __half g_k16[4 * SEQ * DIM];    // 2 MB
__device__ __half g_v16[4 * SEQ * DIM];    // 2 MB

__global__ void cvt_f32_f16(const float* __restrict__ src, __half* __restrict__ dst, int n4) {
    int i = blockIdx.x * blockDim.x + threadIdx.x;
    if (i < n4) {
        float4 v = ((const float4*)src)[i];
        __half2* d = (__half2*)dst + 2 * i;
        d[0] = __floats2half2_rn(v.x, v.y);
        d[1] = __floats2half2_rn(v.z, v.w);
    }
}

__device__ __forceinline__ uint32_t smem_u32(const void* p) {
    uint32_t a;
    asm("{ .reg .u64 t; cvta.to.shared.u64 t, %1; cvt.u32.u64 %0, t; }" : "=r"(a) : "l"(p));
    return a;
}
__device__ __forceinline__ uint32_t pkh(float lo, float hi) {
    uint32_t r; asm("cvt.rn.f16x2.f32 %0, %1, %2;" : "=r"(r) : "f"(hi), "f"(lo)); return r;
}
__device__ __forceinline__ float ex2(float x) {
    float y; asm("ex2.approx.f32 %0, %1;" : "=f"(y) : "f"(x)); return y;
}
__device__ __forceinline__ void sts2f(uint32_t a, float x, float y) {
    asm volatile("st.shared.v2.f32 [%0], {%1,%2};" :: "r"(a), "f"(x), "f"(y));
}
__device__ __forceinline__ void cp16(uint32_t s, const void* g) {
    asm volatile("{ .reg .u64 gg; cvta.to.global.u64 gg, %1;\n\t"
                 "cp.async.cg.shared.global [%0], [gg], 16; }" :: "r"(s), "l"(g));
}
__device__ __forceinline__ void cp_commit() { asm volatile("cp.async.commit_group;" ::: "memory"); }
__device__ __forceinline__ void cp_wait0()  { asm volatile("cp.async.wait_group 0;" ::: "memory"); }
__device__ __forceinline__ void ldsm4(uint32_t* r, uint32_t a) {
    asm volatile("ldmatrix.sync.aligned.m8n8.x4.shared.b16 {%0,%1,%2,%3}, [%4];"
        : "=r"(r[0]), "=r"(r[1]), "=r"(r[2]), "=r"(r[3]) : "r"(a));
}
__device__ __forceinline__ void ldsm4t(uint32_t* r, uint32_t a) {
    asm volatile("ldmatrix.sync.aligned.m8n8.x4.trans.shared.b16 {%0,%1,%2,%3}, [%4];"
        : "=r"(r[0]), "=r"(r[1]), "=r"(r[2]), "=r"(r[3]) : "r"(a));
}
__device__ __forceinline__ void mma16816(float* c, const uint32_t* a, const uint32_t* b) {
    asm volatile("mma.sync.aligned.m16n8k16.row.col.f32.f16.f16.f32 "
        "{%0,%1,%2,%3}, {%4,%5,%6,%7}, {%8,%9}, {%0,%1,%2,%3};"
        : "+f"(c[0]), "+f"(c[1]), "+f"(c[2]), "+f"(c[3])
        : "r"(a[0]), "r"(a[1]), "r"(a[2]), "r"(a[3]), "r"(b[0]), "r"(b[1]));
}

// async copy of one 64x128-fp16 tile pair (K,V) into smem buffers
__device__ __forceinline__ void prefetch_kv(uint32_t KHn, uint32_t VHn,
                                            const __half* Kt, const __half* Vt, int tid) {
    #pragma unroll
    for (int it = 0; it < 4; ++it) {
        int idx = tid + it * 256;        // 1024 chunks of 16B per tile
        int r = idx >> 4, cc = idx & 15;
        uint32_t soff = (uint32_t)(r * SSTR + cc * 16);
        cp16(KHn + soff, Kt + r * DIM + cc * 8);
        cp16(VHn + soff, Vt + r * DIM + cc * 8);
    }
}

__global__ __launch_bounds__(256, 1)
void diff_attn_mma(float* __restrict__ O) {
    extern __shared__ char smc[];
    const uint32_t sb = smem_u32(smc);
    const int tid  = threadIdx.x;
    const int lane = tid & 31;
    const int w    = tid >> 5;
    const int strm = w >> 2;            // 0: stream1 (d 0-63), 1: stream2 (d 64-127)
    const int mrow = (w & 3) << 4;      // warp's 16 q-rows within the 64-row tile

    const int qb  = QBLKS - 1 - blockIdx.x;   // heavy q-blocks first
    const int h   = blockIdx.y;
    const int kvh = h >> 2;

    const __half* Qg = g_q16 + ((size_t)h * SEQ + (size_t)qb * BR) * DIM;
    const __half* Kg = g_k16 + (size_t)kvh * SEQ * DIM;
    const __half* Vg = g_v16 + (size_t)kvh * SEQ * DIM;

    // ---- async-load Q (16KB) + K/V tile 0 ----
    #pragma unroll
    for (int it = 0; it < 4; ++it) {
        int idx = tid + it * 256;
        int r = idx >> 4, cc = idx & 15;
        cp16(sb + QHo + (uint32_t)(r * SSTR + cc * 16), Qg + r * DIM + cc * 8);
    }
    prefetch_kv(sb + kh_(0), sb + vh_(0), Kg, Vg, tid);
    cp_commit();
    cp_wait0();
    __syncthreads();

    const uint32_t d0 = (uint32_t)(strm * 128);   // byte offset of stream's 64 dims

    float o[16][4];
    #pragma unroll
    for (int j = 0; j < 16; ++j) { o[j][0]=0.f; o[j][1]=0.f; o[j][2]=0.f; o[j][3]=0.f; }
    float lac0 = 0.f, lac1 = 0.f;

    const int nkb = qb + 1;
    for (int kb = 0; kb < nkb; ++kb) {
        const int cur = kb & 1, nxt = cur ^ 1;
        const uint32_t KHc = sb + kh_(0) + (uint32_t)cur * BUFSZ;
        const uint32_t VHc = KHc + 17408u;
        const bool pf = (kb + 1 < nkb);
        const bool diag = (kb == qb);
        const int row0 = qb * BR + mrow + (lane >> 2);

        // ---- issue async prefetch of next tile (fire & forget) ----
        if (pf) {
            prefetch_kv(sb + kh_(0) + (uint32_t)nxt * BUFSZ,
                        sb + vh_(0) + (uint32_t)nxt * BUFSZ,
                        Kg + (size_t)(kb + 1) * BC * DIM,
                        Vg + (size_t)(kb + 1) * BC * DIM, tid);
            cp_commit();
        }

        float c[8][4];
        #pragma unroll
        for (int j = 0; j < 8; ++j) { c[j][0]=0.f; c[j][1]=0.f; c[j][2]=0.f; c[j][3]=0.f; }

        // ---- S = Q K^T ----
        #pragma unroll
        for (int kk = 0; kk < 4; ++kk) {
            uint32_t aaddr = (uint32_t)((mrow + (lane & 15)) * SSTR) + d0
                           + (uint32_t)(kk * 32 + (lane >> 4) * 16);
            uint32_t ah[4];
            ldsm4(ah, sb + QHo + aaddr);
            #pragma unroll
            for (int jj = 0; jj < 4; ++jj) {
                uint32_t baddr = (uint32_t)((16 * jj + (lane & 7) + ((lane >> 4) << 3)) * SSTR)
                               + d0 + (uint32_t)(kk * 32 + ((lane >> 3) & 1) * 16);
                uint32_t bh[4];
                ldsm4(bh, KHc + baddr);
                mma16816(c[2*jj],   ah, bh);
                mma16816(c[2*jj+1], ah, bh + 2);
            }
        }

        // ---- two pipelined halves: softmax+convert then PV ----
        #pragma unroll
        for (int half = 0; half < 2; ++half) {
            #pragma unroll
            for (int jx = 0; jx < 4; ++jx) {
                const int j = half * 4 + jx;
                int colb = kb * BC + 8 * j + 2 * (lane & 3);
                float p0 = ex2(c[j][0] * EX2C), p1 = ex2(c[j][1] * EX2C);
                float p2 = ex2(c[j][2] * EX2C), p3 = ex2(c[j][3] * EX2C);
                if (diag) {
                    if (colb     > row0)     p0 = 0.f;
                    if (colb + 1 > row0)     p1 = 0.f;
                    if (colb     > row0 + 8) p2 = 0.f;
                    if (colb + 1 > row0 + 8) p3 = 0.f;
                }
                c[j][0] = p0; c[j][1] = p1; c[j][2] = p2; c[j][3] = p3;
                lac0 += p0 + p1;
                lac1 += p2 + p3;
            }

            uint32_t ph[2][4];
            #pragma unroll
            for (int kx = 0; kx < 2; ++kx) {
                const int kk = half * 2 + kx;
                const float* f0 = c[2*kk];
                const float* f1 = c[2*kk+1];
                ph[kx][0] = pkh(f0[0], f0[1]);
                ph[kx][1] = pkh(f0[2], f0[3]);
                ph[kx][2] = pkh(f1[0], f1[1]);
                ph[kx][3] = pkh(f1[2], f1[3]);
            }

            #pragma unroll
            for (int kx = 0; kx < 2; ++kx) {
                const int kk = half * 2 + kx;
                #pragma unroll
                for (int jj = 0; jj < 8; ++jj) {
                    uint32_t vaddr = (uint32_t)((16 * kk + (lane & 15)) * SSTR)
                                   + (uint32_t)(jj * 32 + (lane >> 4) * 16);
                    uint32_t vh4[4];
                    ldsm4t(vh4, VHc + vaddr);
                    mma16816(o[2*jj],   ph[kx], vh4);
                    mma16816(o[2*jj+1], ph[kx], vh4 + 2);
                }
            }
        }

        if (pf) cp_wait0();
        __syncthreads();   // cur reads done; nxt writes complete+visible
    }

    // ---- epilogue: O frags -> smem (f32), l sums, combine streams ----
    const uint32_t ob = sb + (strm ? kh_(1) : kh_(0));   // reuse K/V regions
    const int r0 = mrow + (lane >> 2);
    #pragma unroll
    for (int j = 0; j < 16; ++j) {
        uint32_t cb = (uint32_t)((8 * j + 2 * (lane & 3)) * 4);
        sts2f(ob + (uint32_t)(r0 * OSTR) + cb,       o[j][0], o[j][1]);
        sts2f(ob + (uint32_t)((r0 + 8) * OSTR) + cb, o[j][2], o[j][3]);
    }
    lac0 += __shfl_xor_sync(0xffffffffu, lac0, 1);
    lac0 += __shfl_xor_sync(0xffffffffu, lac0, 2);
    lac1 += __shfl_xor_sync(0xffffffffu, lac1, 1);
    lac1 += __shfl_xor_sync(0xffffffffu, lac1, 2);
    float* ls = (float*)(smc + LSo);
    if ((lane & 3) == 0) {
        ls[strm * 64 + r0]     = lac0;
        ls[strm * 64 + r0 + 8] = lac1;
    }
    __syncthreads();

    const int er = tid >> 2;
    const int cq = (tid & 3) * 32;
    const float i1 = OUT_SCALE / ls[er];
    const float i2 = OUT_SCALE * LAMBDA / ls[64 + er];
    float* Og = O + ((size_t)h * SEQ + (size_t)qb * BR + er) * DIM + cq;
    #pragma unroll
    for (int u = 0; u < 8; ++u) {
        float4 a = *(const float4*)(smc + kh_(0) + er * OSTR + (cq + 4 * u) * 4);
        float4 b = *(const float4*)(smc + kh_(1) + er * OSTR + (cq + 4 * u) * 4);
        float4 ov;
        ov.x = a.x * i1 - b.x * i2;
        ov.y = a.y * i1 - b.y * i2;
        ov.z = a.z * i1 - b.z * i2;
        ov.w = a.w * i1 - b.w * i2;
        *(float4*)(Og + 4 * u) = ov;
    }
}

extern "C" void kernel_launch(void* const* d_in, const int* in_sizes, int n_in,
                              void* d_out, int out_size) {
    const float* Q = (const float*)d_in[0];
    const float* K = (const float*)d_in[1];
    const float* V = (const float*)d_in[2];
    float* O = (float*)d_out;

    // resolve device buffer addresses (host-side, cached per process is fine:
    // deterministic, no allocation)
    __half *q16p, *k16p, *v16p;
    cudaGetSymbolAddress((void**)&q16p, g_q16);
    cudaGetSymbolAddress((void**)&k16p, g_k16);
    cudaGetSymbolAddress((void**)&v16p, g_v16);

    const int nq4 = 16 * SEQ * DIM / 4;   // 1,048,576
    const int nk4 = 4  * SEQ * DIM / 4;   // 262,144
    cvt_f32_f16<<<(nq4 + 255) / 256, 256>>>(Q, q16p, nq4);
    cvt_f32_f16<<<(nk4 + 255) / 256, 256>>>(K, k16p, nk4);
    cvt_f32_f16<<<(nk4 + 255) / 256, 256>>>(V, v16p, nk4);

    cudaFuncSetAttribute(diff_attn_mma,
                         cudaFuncAttributeMaxDynamicSharedMemorySize, SMEM_TOTAL);
    dim3 grid(QBLKS, 16);   // (32, 16) = 512 CTAs, heavy first
    diff_attn_mma<<<grid, 256, SMEM_TOTAL>>>(O);
}